// round 3
// baseline (speedup 1.0000x reference)
#include <cuda_runtime.h>

// ---------------------------------------------------------------------------
// SpMiddleFHD: subm3x3x3 conv 128->16 relu, subm 16->16 relu, strided (s=2,p=1)
// conv 16->32 into dense (B,Do,Ho,Wo,32) with relu.
// B=2, Dz=41, Hy=400, Wx=352, N=40000, Do=21, Ho=200, Wo=176.
//
// Grid hash: idx+1 in uint16 (0 = empty). Device globals are zero-init at
// load; a tail kernel clears the 40000 touched cells each call, preserving
// the all-zero invariant across graph replays.
//
// Output pass is a GATHER (no atomics): for each (point, valid downsampled
// voxel) pair, re-enumerate all contributors of that voxel via the grid and
// write the full sum. Duplicate warps compute bit-identical values (fixed
// k-order), so racing stores are benign. The 189MB output zero-fill runs on a
// side stream, overlapped with the conv chain, joined before the gather.
// ---------------------------------------------------------------------------

namespace {
constexpr int kB  = 2;
constexpr int kDZ = 41, kHY = 400, kWX = 352;
constexpr int kGD = kDZ + 2, kGH = kHY + 2, kGW = kWX + 2;
constexpr int kN  = 40000;
constexpr int kDO = 21, kHO = 200, kWO = 176;
constexpr int kGridCells = kB * kGD * kGH * kGW;  // 12,238,488
}

__device__ unsigned short g_grid[kGridCells];     // 24.5 MB, idx+1 (0 empty)
__device__ int   g_cnt[kN];
__device__ int   g_list[kN * 27];                 // packed (k<<16)|idx
__device__ __align__(16) float g_x1[kN * 16];
__device__ __align__(16) float g_x2[kN * 16];

__device__ __forceinline__ int cell_of(int4 c, int dk, int dy, int dx) {
    return ((c.x * kGD + c.y + dk) * kGH + c.z + dy) * kGW + c.w + dx;
}

// ---------------------------------------------------------------------------
__global__ void k_scatter(const int4* __restrict__ coors) {
    int n = blockIdx.x * blockDim.x + threadIdx.x;
    if (n >= kN) return;
    int4 c = __ldg(&coors[n]);
    g_grid[cell_of(c, 1, 1, 1)] = (unsigned short)(n + 1);
}

__global__ void k_clear(const int4* __restrict__ coors) {
    int n = blockIdx.x * blockDim.x + threadIdx.x;
    if (n >= kN) return;
    int4 c = __ldg(&coors[n]);
    g_grid[cell_of(c, 1, 1, 1)] = 0;
}

// ---------------------------------------------------------------------------
// conv1 (128->16, relu) fused with neighbor-list construction.
__global__ void k_conv1(const float* __restrict__ feat,
                        const int4* __restrict__ coors,
                        const float* __restrict__ W1) {
    int n    = blockIdx.x * (blockDim.x >> 5) + (threadIdx.x >> 5);
    int lane = threadIdx.x & 31;
    if (n >= kN) return;

    int4 c = __ldg(&coors[n]);

    int v = -1;
    if (lane < 27) {
        int dk = lane / 9, dy = (lane / 3) % 3, dx = lane % 3;
        v = (int)g_grid[cell_of(c, dk, dy, dx)] - 1;
    }
    unsigned ball = __ballot_sync(0xffffffffu, v >= 0);
    int pre = __popc(ball & ((1u << lane) - 1));
    if (v >= 0) g_list[n * 27 + pre] = (lane << 16) | v;
    if (lane == 0) g_cnt[n] = __popc(ball);

    float4 a0 = make_float4(0,0,0,0), a1 = a0, a2 = a0, a3 = a0;
    const float4* fv = reinterpret_cast<const float4*>(feat);
    const float4* wv = reinterpret_cast<const float4*>(W1);

    for (unsigned m = ball; m; m &= m - 1) {
        int k   = __ffs(m) - 1;
        int idx = __shfl_sync(0xffffffffu, v, k);
        float4 f = __ldcg(&fv[idx * 32 + lane]);
        const float4* wk = &wv[(k * 128 + lane * 4) * 4];
        float4 w;
        w = __ldg(wk + 0);  a0.x+=f.x*w.x; a0.y+=f.x*w.y; a0.z+=f.x*w.z; a0.w+=f.x*w.w;
        w = __ldg(wk + 1);  a1.x+=f.x*w.x; a1.y+=f.x*w.y; a1.z+=f.x*w.z; a1.w+=f.x*w.w;
        w = __ldg(wk + 2);  a2.x+=f.x*w.x; a2.y+=f.x*w.y; a2.z+=f.x*w.z; a2.w+=f.x*w.w;
        w = __ldg(wk + 3);  a3.x+=f.x*w.x; a3.y+=f.x*w.y; a3.z+=f.x*w.z; a3.w+=f.x*w.w;
        w = __ldg(wk + 4);  a0.x+=f.y*w.x; a0.y+=f.y*w.y; a0.z+=f.y*w.z; a0.w+=f.y*w.w;
        w = __ldg(wk + 5);  a1.x+=f.y*w.x; a1.y+=f.y*w.y; a1.z+=f.y*w.z; a1.w+=f.y*w.w;
        w = __ldg(wk + 6);  a2.x+=f.y*w.x; a2.y+=f.y*w.y; a2.z+=f.y*w.z; a2.w+=f.y*w.w;
        w = __ldg(wk + 7);  a3.x+=f.y*w.x; a3.y+=f.y*w.y; a3.z+=f.y*w.z; a3.w+=f.y*w.w;
        w = __ldg(wk + 8);  a0.x+=f.z*w.x; a0.y+=f.z*w.y; a0.z+=f.z*w.z; a0.w+=f.z*w.w;
        w = __ldg(wk + 9);  a1.x+=f.z*w.x; a1.y+=f.z*w.y; a1.z+=f.z*w.z; a1.w+=f.z*w.w;
        w = __ldg(wk + 10); a2.x+=f.z*w.x; a2.y+=f.z*w.y; a2.z+=f.z*w.z; a2.w+=f.z*w.w;
        w = __ldg(wk + 11); a3.x+=f.z*w.x; a3.y+=f.z*w.y; a3.z+=f.z*w.z; a3.w+=f.z*w.w;
        w = __ldg(wk + 12); a0.x+=f.w*w.x; a0.y+=f.w*w.y; a0.z+=f.w*w.z; a0.w+=f.w*w.w;
        w = __ldg(wk + 13); a1.x+=f.w*w.x; a1.y+=f.w*w.y; a1.z+=f.w*w.z; a1.w+=f.w*w.w;
        w = __ldg(wk + 14); a2.x+=f.w*w.x; a2.y+=f.w*w.y; a2.z+=f.w*w.z; a2.w+=f.w*w.w;
        w = __ldg(wk + 15); a3.x+=f.w*w.x; a3.y+=f.w*w.y; a3.z+=f.w*w.z; a3.w+=f.w*w.w;
    }

    float vals[16] = {a0.x,a0.y,a0.z,a0.w, a1.x,a1.y,a1.z,a1.w,
                      a2.x,a2.y,a2.z,a2.w, a3.x,a3.y,a3.z,a3.w};
    float res = 0.f;
    #pragma unroll
    for (int d = 0; d < 16; d++) {
        float t = vals[d];
        t += __shfl_xor_sync(0xffffffffu, t, 16);
        t += __shfl_xor_sync(0xffffffffu, t, 8);
        t += __shfl_xor_sync(0xffffffffu, t, 4);
        t += __shfl_xor_sync(0xffffffffu, t, 2);
        t += __shfl_xor_sync(0xffffffffu, t, 1);
        if (lane == d) res = t;
    }
    if (lane < 16) g_x1[n * 16 + lane] = fmaxf(res, 0.f);
}

// ---------------------------------------------------------------------------
// conv2 (16->16, relu): 16 lanes per point, lane = output channel.
// W2 column reads are coalesced (64B per 16-lane group); x reads broadcast.
__global__ void k_conv2(const float* __restrict__ W2) {
    int t = blockIdx.x * blockDim.x + threadIdx.x;
    int n = t >> 4;
    int d = t & 15;
    if (n >= kN) return;

    int cnt = g_cnt[n];
    float acc = 0.f;
    for (int j = 0; j < cnt; j++) {
        int p   = g_list[n * 27 + j];
        int idx = p & 0xffff;
        int k   = p >> 16;
        const float* xr = &g_x1[idx * 16];
        const float* wr = &W2[k * 256 + d];
        #pragma unroll
        for (int cc = 0; cc < 16; cc++)
            acc += xr[cc] * __ldg(&wr[cc * 16]);
    }
    g_x2[n * 16 + d] = fmaxf(acc, 0.f);
}

// ---------------------------------------------------------------------------
// conv3 (16->32) downsample as an idempotent GATHER. Warp per point; for each
// of its valid output voxels, lanes 0..26 probe the 27 input cells feeding
// that voxel, then all 32 lanes (lane = out channel) sum contributions in
// fixed k-order and store. Duplicate voxel visits write identical bits.
__global__ void k_conv3_gather(const int4* __restrict__ coors,
                               const float* __restrict__ W3,
                               float* __restrict__ out) {
    int n    = blockIdx.x * (blockDim.x >> 5) + (threadIdx.x >> 5);
    int lane = threadIdx.x & 31;
    if (n >= kN) return;

    int4 c = __ldg(&coors[n]);
    int j  = lane / 9, jy = (lane / 3) % 3, jx = lane % 3;   // probe offsets

    for (int dk = 0; dk < 3; dk++) {
        int oz = c.y + 1 - dk;
        if (oz < 0 || (oz & 1)) continue;
        int pz = oz >> 1;
        if (pz >= kDO) continue;
        for (int dy = 0; dy < 3; dy++) {
            int oy = c.z + 1 - dy;
            if (oy < 0 || (oy & 1)) continue;
            int py = oy >> 1;
            if (py >= kHO) continue;
            for (int dx = 0; dx < 3; dx++) {
                int ox = c.w + 1 - dx;
                if (ox < 0 || (ox & 1)) continue;
                int px = ox >> 1;
                if (px >= kWO) continue;

                // probe the 27 input cells feeding voxel (pz,py,px):
                // input z' = 2pz-1+j -> padded index 2pz+j (in [0,kGD))
                int vm = -1;
                if (lane < 27) {
                    int iz = 2 * pz + j, iy = 2 * py + jy, ix = 2 * px + jx;
                    vm = (int)g_grid[((c.x * kGD + iz) * kGH + iy) * kGW + ix] - 1;
                }
                unsigned ball = __ballot_sync(0xffffffffu, vm >= 0);

                float acc = 0.f;
                for (unsigned m = ball; m; m &= m - 1) {
                    int k   = __ffs(m) - 1;                  // ascending k
                    int idx = __shfl_sync(0xffffffffu, vm, k);
                    const float* xr = &g_x2[idx * 16];
                    const float* wr = &W3[k * 512 + lane];
                    #pragma unroll
                    for (int cc = 0; cc < 16; cc++)
                        acc += xr[cc] * __ldg(&wr[cc * 32]);
                }
                int base = ((c.x * kDO + pz) * kHO + py) * kWO + px;
                out[base * 32 + lane] = fmaxf(acc, 0.f);
            }
        }
    }
}

// ---------------------------------------------------------------------------
extern "C" void kernel_launch(void* const* d_in, const int* in_sizes, int n_in,
                              void* d_out, int out_size) {
    const float* feat  = (const float*)d_in[0];
    const int4*  coors = (const int4*) d_in[1];
    const float* W1    = (const float*)d_in[2];
    const float* W2    = (const float*)d_in[3];
    const float* W3    = (const float*)d_in[4];
    float*       out   = (float*)d_out;
    (void)in_sizes; (void)n_in;

    static cudaStream_t side = nullptr;
    static cudaEvent_t  efork = nullptr, ejoin = nullptr;
    if (!side) {
        cudaStreamCreateWithFlags(&side, cudaStreamNonBlocking);
        cudaEventCreateWithFlags(&efork, cudaEventDisableTiming);
        cudaEventCreateWithFlags(&ejoin, cudaEventDisableTiming);
    }

    // Fork: zero the 189MB output on the side stream, overlapped with the
    // conv chain; join before the gather writes the output.
    cudaEventRecord(efork, 0);
    cudaStreamWaitEvent(side, efork, 0);
    cudaMemsetAsync(out, 0, (size_t)out_size * sizeof(float), side);
    cudaEventRecord(ejoin, side);

    k_scatter <<<(kN + 255) / 256, 256>>>(coors);
    k_conv1   <<<(kN + 7) / 8, 256>>>(feat, coors, W1);
    k_conv2   <<<(kN * 16 + 255) / 256, 256>>>(W2);

    cudaStreamWaitEvent(0, ejoin, 0);
    k_conv3_gather <<<(kN + 7) / 8, 256>>>(coors, W3, out);
    k_clear        <<<(kN + 255) / 256, 256>>>(coors);
}